// round 6
// baseline (speedup 1.0000x reference)
#include <cuda_runtime.h>

// VelocityLoss on GB300 — coalesced comp-per-lane layout (R5 + index fix).
//
// Warp loads each row as 5 coalesced 32-lane LDGs: x_g = row[32g+lane].
//  - velocity: v_c=(cur-prev)*std[c] computed in pos layout (groups 0..2)
//  - pred_vel col = 77+c  =>  lane holding col q needs v_{q-77}, whose
//    mean/std index is 72+(q-77) = q-5. Rotation: 19 == -13 (mod 32), so
//    r_g = shfl(v_g,(lane+19)&31) realigns all 72 components:
//      x2 (cols 64..95): lane>=13 uses r0, consts at [59+lane]
//      x3 (cols 96..127): lane<13 ? r0 : r1, consts at [91+lane]
//      x4 (cols 128..148): lane<21, lane<13 ? r1 : r2, consts at [123+lane]
//  - norms: v^2 via per-warp smem slab (stride-3 LDS conflict-free), R2's
//    part-aligned joint remap; 3 shuffles give all 5 part sums.
// Double-buffered slabs -> one __syncwarp per 2-row batch.

namespace {
constexpr int B_  = 512;
constexpr int S_  = 480;
constexpr int F_  = 149;
constexpr int VF_ = 5;
constexpr int CH  = 16;                   // rows per warp chunk
constexpr int CPB = S_ / CH;              // 30
constexpr int WPB = 8;                    // 256 threads
constexpr int NBLK = B_ * CPB / WPB;      // 1920
}

__device__ double g_acc[3] = {0.0, 0.0, 0.0};
__device__ unsigned int g_ticket = 0;

// lane -> joint, part groups shuffle-aligned (lanes 0-7 part0, 8-11 p1,
// 12-15 p2, 16-19 p3, 20-23 p4)
__constant__ int c_j[24] = {
    8, 9, 10, 11, 12, 21, 22, 23,
    0, 1, 2, 3,
    4, 5, 6, 7,
    13, 14, 15, 16,
    17, 18, 19, 20
};
__constant__ float c_wl[24] = {
    1.f/9, 1.f/9, 1.f/9, 1.f/9, 1.f/9, 1.f/9, 2.f/9, 1.f/9,
    0.1f, 0.2f, 0.3f, 0.4f,
    0.1f, 0.2f, 0.3f, 0.4f,
    0.1f, 0.2f, 0.3f, 0.4f,
    0.1f, 0.2f, 0.3f, 0.4f
};

__global__ void __launch_bounds__(256, 4) vel_loss_coal(
    const float* __restrict__ pred,   // (B, S, F)
    const float* __restrict__ tvft,   // (B, S+1, VF)
    const float* __restrict__ meanv,  // (F,)
    const float* __restrict__ stdv,   // (F,)
    float* __restrict__ out)
{
    __shared__ float su[WPB][4][72];          // [warp][slab][comp]
    __shared__ double sA[WPB], sB[WPB], sC[WPB];

    const int tid  = threadIdx.x;
    const int lane = tid & 31;
    const int warp = tid >> 5;
    const int idx  = blockIdx.x * WPB + warp;
    const int b    = idx / CPB;
    const int s0   = (idx % CPB) * CH;
    const unsigned FULL = 0xffffffffu;

    // per-lane constants (comp/column layout)
    const float sp0 = stdv[lane];
    const float sp1 = stdv[32 + lane];
    const float sp2 = (lane < 8) ? stdv[64 + lane] : 0.f;
    // vel-norm constants: pred_vel col q -> mean/std index q-5
    float mvq2 = 0.f, rvq2 = 0.f;
    if (lane >= 13) { mvq2 = meanv[59 + lane]; rvq2 = 1.0f / stdv[59 + lane]; }
    const float mvq3 = meanv[91 + lane];
    const float rvq3 = 1.0f / stdv[91 + lane];
    float mvq4 = 0.f, rvq4 = 0.f;
    if (lane < 21) { mvq4 = meanv[123 + lane]; rvq4 = 1.0f / stdv[123 + lane]; }

    int jj = 0; float w = 0.f;
    if (lane < 24) { jj = c_j[lane] * 3; w = c_wl[lane]; }
    int pidx = -1;
    if      (lane == 0)  pidx = 0;
    else if (lane == 8)  pidx = 1;
    else if (lane == 12) pidx = 2;
    else if (lane == 16) pidx = 3;
    else if (lane == 20) pidx = 4;
    float mf = 0.f, rf = 0.f;
    if (pidx >= 0) { mf = meanv[144 + pidx]; rf = 1.0f / stdv[144 + pidx]; }

    float accA = 0.f, accB = 0.f, accC = 0.f;
    float p0 = 0.f, p1 = 0.f, p2 = 0.f;

    const float* trbase = tvft + ((size_t)b * (S_ + 1)) * VF_;

    // ---- prev-row init / s==0 special term ----
    int sBeg = s0;
    {
        const float* r0p = pred + ((size_t)(b * S_ + s0)) * F_;
        if (s0 == 0) {
            const float x0 = r0p[lane];
            const float x1 = r0p[32 + lane];
            const float x2 = r0p[64 + lane];
            const float x3 = r0p[96 + lane];
            const float x4 = (lane < 21) ? r0p[128 + lane] : 0.f;
            p0 = x0; p1 = x1; p2 = x2;
            if (lane >= 13) accB += x2 * x2;
            accB += x3 * x3;
            accB += x4 * x4;           // lanes>=21 contribute 0
            sBeg = 1;
        } else {
            const float* rp = r0p - F_;
            p0 = rp[lane];
            p1 = rp[32 + lane];
            p2 = (lane < 8) ? rp[64 + lane] : 0.f;
        }
    }

    // per-row compute: MSE term + v^2 slab write; updates p
    auto comprow = [&](float x0, float x1, float x2, float x3, float x4,
                       float* __restrict__ slab) {
        const float v0 = (x0 - p0) * sp0;
        const float v1 = (x1 - p1) * sp1;
        const float v2 = (x2 - p2) * sp2;
        const int src = (lane + 19) & 31;
        const float r0 = __shfl_sync(FULL, v0, src);
        const float r1 = __shfl_sync(FULL, v1, src);
        const float r2 = __shfl_sync(FULL, v2, src);
        const float vq3 = (lane < 13) ? r0 : r1;
        const float vq4 = (lane < 13) ? r1 : r2;
        if (lane >= 13) { const float d = x2 - (r0 - mvq2) * rvq2; accA += d * d; }
        { const float d = x3 - (vq3 - mvq3) * rvq3; accA += d * d; }
        if (lane < 21)  { const float d = x4 - (vq4 - mvq4) * rvq4; accA += d * d; }
        slab[lane]      = v0 * v0;
        slab[32 + lane] = v1 * v1;
        if (lane < 8) slab[64 + lane] = v2 * v2;
        p0 = x0; p1 = x1; p2 = x2;
    };

    auto normrow = [&](const float* __restrict__ slab, float tr) {
        float contrib = 0.f;
        if (lane < 24)
            contrib = sqrtf(slab[jj] + slab[jj + 1] + slab[jj + 2]) * w;
        float g4 = contrib + __shfl_xor_sync(FULL, contrib, 1);
        g4 += __shfl_xor_sync(FULL, g4, 2);
        const float g8 = g4 + __shfl_xor_sync(FULL, g4, 4);
        if (pidx >= 0) {
            const float f = (pidx == 0) ? g8 : g4;
            const float d = tr - (f - mf) * rf;
            accC += d * d;
        }
    };

    const int sEnd = s0 + CH;
    int s = sBeg;
    int buf = 0;

    for (; s + 2 <= sEnd; s += 2) {
        const float* rA = pred + ((size_t)(b * S_ + s)) * F_;
        const float* rB = rA + F_;
        // front-issued coalesced loads (10 wavefronts)
        const float a0 = rA[lane],      a1 = rA[32 + lane], a2 = rA[64 + lane];
        const float a3 = rA[96 + lane], a4 = (lane < 21) ? rA[128 + lane] : 0.f;
        const float b0 = rB[lane],      b1 = rB[32 + lane], b2 = rB[64 + lane];
        const float b3 = rB[96 + lane], b4 = (lane < 21) ? rB[128 + lane] : 0.f;
        float trA = 0.f, trB = 0.f;
        if (pidx >= 0) {
            trA = trbase[(size_t)s * VF_ + pidx];
            trB = trbase[(size_t)(s + 1) * VF_ + pidx];
        }
        float* slabA = su[warp][buf * 2 + 0];
        float* slabB = su[warp][buf * 2 + 1];
        comprow(a0, a1, a2, a3, a4, slabA);
        comprow(b0, b1, b2, b3, b4, slabB);
        __syncwarp();
        normrow(slabA, trA);
        normrow(slabB, trB);
        buf ^= 1;
    }
    // tail (odd row count: only the s0==0 chunk)
    if (s < sEnd) {
        const float* rA = pred + ((size_t)(b * S_ + s)) * F_;
        const float a0 = rA[lane],      a1 = rA[32 + lane], a2 = rA[64 + lane];
        const float a3 = rA[96 + lane], a4 = (lane < 21) ? rA[128 + lane] : 0.f;
        float trA = 0.f;
        if (pidx >= 0) trA = trbase[(size_t)s * VF_ + pidx];
        float* slabA = su[warp][buf * 2];
        comprow(a0, a1, a2, a3, a4, slabA);
        __syncwarp();
        normrow(slabA, trA);
    }

    // ---- reductions ----
    #pragma unroll
    for (int off = 16; off; off >>= 1) {
        accA += __shfl_xor_sync(FULL, accA, off);
        accB += __shfl_xor_sync(FULL, accB, off);
        accC += __shfl_xor_sync(FULL, accC, off);
    }
    if (lane == 0) {
        sA[warp] = (double)accA;
        sB[warp] = (double)accB;
        sC[warp] = (double)accC;
    }
    __syncthreads();

    if (warp == 0) {
        double a  = (lane < WPB) ? sA[lane] : 0.0;
        double bb = (lane < WPB) ? sB[lane] : 0.0;
        double c  = (lane < WPB) ? sC[lane] : 0.0;
        #pragma unroll
        for (int off = 4; off; off >>= 1) {
            a  += __shfl_xor_sync(FULL, a, off);
            bb += __shfl_xor_sync(FULL, bb, off);
            c  += __shfl_xor_sync(FULL, c, off);
        }
        if (lane == 0) {
            atomicAdd(&g_acc[0], a);
            atomicAdd(&g_acc[1], bb);
            atomicAdd(&g_acc[2], c);
            __threadfence();
            const unsigned t = atomicAdd(&g_ticket, 1u);
            if (t == (unsigned)(NBLK - 1)) {
                __threadfence();
                volatile double* ga = g_acc;
                const double A  = ga[0];
                const double B0 = ga[1];
                const double C  = ga[2];
                const double nA = (double)B_ * (double)(S_ - 1) * 72.0;
                const double nB = (double)B_ * 72.0;
                const double nC = (double)B_ * (double)(S_ - 1) * (double)VF_;
                const double loss1 = 10.0 * A / nA + 20.0 * B0 / nB;
                const double loss2 = 10.0 * C / nC;
                out[0] = (float)(2.0 * loss1 + 1.5 * loss2);
                ga[0] = 0.0; ga[1] = 0.0; ga[2] = 0.0;
                g_ticket = 0;
            }
        }
    }
}

extern "C" void kernel_launch(void* const* d_in, const int* in_sizes, int n_in,
                              void* d_out, int out_size) {
    const float* pred = (const float*)d_in[0];   // predict_seq (B,S,F)
    // d_in[1] = _train_x1 (unused), d_in[2] = _train_x2 (unused)
    const float* tvft = (const float*)d_in[3];   // _true_vel_factor (B,S+1,VF)
    const float* mean = (const float*)d_in[4];   // _mean (F,)
    const float* stdv = (const float*)d_in[5];   // _std (F,)

    vel_loss_coal<<<NBLK, 256>>>(pred, tvft, mean, stdv, (float*)d_out);
}

// round 7
// speedup vs baseline: 1.0033x; 1.0033x over previous
#include <cuda_runtime.h>

// VelocityLoss on GB300 — R4 direct-LDG joint-per-lane layout + software
// pipelining: batch t+1's loads are issued BEFORE batch t's shuffle phase
// (double-buffered register arrays), so load latency and shuffle latency
// hide each other.

namespace {
constexpr int B_  = 512;
constexpr int S_  = 480;
constexpr int F_  = 149;
constexpr int VF_ = 5;
constexpr int CH  = 16;                   // rows per warp chunk
constexpr int CPB = S_ / CH;              // 30
constexpr int WPB = 8;                    // 256 threads
constexpr int NBLK = B_ * CPB / WPB;      // 1920
}

__device__ double g_acc[3] = {0.0, 0.0, 0.0};
__device__ unsigned int g_ticket = 0;

// lane -> joint, part groups shuffle-aligned:
// lanes 0-7 part0, 8-11 part1, 12-15 part2, 16-19 part3, 20-23 part4
__constant__ int c_j[24] = {
    8, 9, 10, 11, 12, 21, 22, 23,
    0, 1, 2, 3,
    4, 5, 6, 7,
    13, 14, 15, 16,
    17, 18, 19, 20
};
__constant__ float c_wl[24] = {
    1.f/9, 1.f/9, 1.f/9, 1.f/9, 1.f/9, 1.f/9, 2.f/9, 1.f/9,
    0.1f, 0.2f, 0.3f, 0.4f,
    0.1f, 0.2f, 0.3f, 0.4f,
    0.1f, 0.2f, 0.3f, 0.4f,
    0.1f, 0.2f, 0.3f, 0.4f
};

__global__ void __launch_bounds__(256, 3) vel_loss_pipe(
    const float* __restrict__ pred,   // (B, S, F)
    const float* __restrict__ tvft,   // (B, S+1, VF)
    const float* __restrict__ meanv,  // (F,)
    const float* __restrict__ stdv,   // (F,)
    float* __restrict__ out)
{
    const int tid  = threadIdx.x;
    const int lane = tid & 31;
    const int warp = tid >> 5;
    const int idx  = blockIdx.x * WPB + warp;
    const int b    = idx / CPB;
    const int s0   = (idx % CPB) * CH;
    const unsigned FULL = 0xffffffffu;

    // per-lane joint parameters
    int jj = 0; float w = 0.f;
    float sp0 = 0, sp1 = 0, sp2 = 0, mv0 = 0, mv1 = 0, mv2 = 0, rv0 = 0, rv1 = 0, rv2 = 0;
    const bool act = (lane < 24);
    if (act) {
        jj = c_j[lane] * 3;
        w  = c_wl[lane];
        sp0 = stdv[jj];       sp1 = stdv[jj + 1];       sp2 = stdv[jj + 2];
        mv0 = meanv[72 + jj]; mv1 = meanv[72 + jj + 1]; mv2 = meanv[72 + jj + 2];
        rv0 = 1.0f / stdv[72 + jj];
        rv1 = 1.0f / stdv[72 + jj + 1];
        rv2 = 1.0f / stdv[72 + jj + 2];
    }
    int pidx = -1;
    if      (lane == 0)  pidx = 0;
    else if (lane == 8)  pidx = 1;
    else if (lane == 12) pidx = 2;
    else if (lane == 16) pidx = 3;
    else if (lane == 20) pidx = 4;
    float mf = 0.f, rf = 0.f;
    if (pidx >= 0) { mf = meanv[144 + pidx]; rf = 1.0f / stdv[144 + pidx]; }

    float accA = 0.f, accB = 0.f, accC = 0.f;
    float p0 = 0.f, p1 = 0.f, p2 = 0.f;

    const float* trbase = tvft + ((size_t)b * (S_ + 1)) * VF_;

    // scalar one-row step (prologue rows of the s0==0 chunk)
    auto scalarRow = [&](int s) {
        const float* r = pred + ((size_t)(b * S_ + s)) * F_;
        float contrib = 0.f;
        if (act) {
            const float cc0 = r[jj], cc1 = r[jj + 1], cc2 = r[jj + 2];
            const float qq0 = r[77 + jj], qq1 = r[78 + jj], qq2 = r[79 + jj];
            const float v0 = (cc0 - p0) * sp0;
            const float v1 = (cc1 - p1) * sp1;
            const float v2 = (cc2 - p2) * sp2;
            const float d0 = qq0 - (v0 - mv0) * rv0;
            const float d1 = qq1 - (v1 - mv1) * rv1;
            const float d2 = qq2 - (v2 - mv2) * rv2;
            accA += d0 * d0 + d1 * d1 + d2 * d2;
            contrib = sqrtf(v0 * v0 + v1 * v1 + v2 * v2) * w;
            p0 = cc0; p1 = cc1; p2 = cc2;
        }
        float g4v = contrib;
        g4v += __shfl_xor_sync(FULL, g4v, 1);
        g4v += __shfl_xor_sync(FULL, g4v, 2);
        const float g8v = g4v + __shfl_xor_sync(FULL, g4v, 4);
        if (pidx >= 0) {
            const float f = (pidx == 0) ? g8v : g4v;
            const float d = trbase[(size_t)s * VF_ + pidx] - (f - mf) * rf;
            accC += d * d;
        }
    };

    // chunk prologue
    int sBeg;
    {
        const float* r0 = pred + ((size_t)(b * S_ + s0)) * F_;
        if (s0 == 0) {
            if (act) {
                p0 = r0[jj]; p1 = r0[jj + 1]; p2 = r0[jj + 2];
                const float q0 = r0[77 + jj], q1 = r0[78 + jj], q2 = r0[79 + jj];
                accB = q0 * q0 + q1 * q1 + q2 * q2;
            }
            scalarRow(1); scalarRow(2); scalarRow(3);
            sBeg = 4;
        } else {
            if (act) {
                const float* rp = r0 - F_;
                p0 = rp[jj]; p1 = rp[jj + 1]; p2 = rp[jj + 2];
            }
            sBeg = s0;
        }
    }
    const int nB = (s0 + CH - sBeg) >> 2;   // 3 (s0==0) or 4

    // double-buffered batch registers
    float C0[2][4], C1[2][4], C2[2][4], Q0[2][4], Q1[2][4], Q2[2][4];

    auto loadB = [&](int s, int bi) {
        const float* r = pred + ((size_t)(b * S_ + s)) * F_;
        #pragma unroll
        for (int k = 0; k < 4; ++k) {
            const float* rr = r + (size_t)k * F_;
            if (act) {
                C0[bi][k] = rr[jj];      C1[bi][k] = rr[jj + 1];  C2[bi][k] = rr[jj + 2];
                Q0[bi][k] = rr[77 + jj]; Q1[bi][k] = rr[78 + jj]; Q2[bi][k] = rr[79 + jj];
            }
        }
    };

    auto computeB = [&](int s, int bi) {
        float tr[4] = {0.f, 0.f, 0.f, 0.f};
        if (pidx >= 0) {
            #pragma unroll
            for (int k = 0; k < 4; ++k)
                tr[k] = trbase[(size_t)(s + k) * VF_ + pidx];
        }
        float contrib[4];
        #pragma unroll
        for (int k = 0; k < 4; ++k) {
            contrib[k] = 0.f;
            if (act) {
                const float v0 = (C0[bi][k] - p0) * sp0;
                const float v1 = (C1[bi][k] - p1) * sp1;
                const float v2 = (C2[bi][k] - p2) * sp2;
                const float d0 = Q0[bi][k] - (v0 - mv0) * rv0;
                const float d1 = Q1[bi][k] - (v1 - mv1) * rv1;
                const float d2 = Q2[bi][k] - (v2 - mv2) * rv2;
                accA += d0 * d0 + d1 * d1 + d2 * d2;
                contrib[k] = sqrtf(v0 * v0 + v1 * v1 + v2 * v2) * w;
                p0 = C0[bi][k]; p1 = C1[bi][k]; p2 = C2[bi][k];
            }
        }
        float g4v[4], g8v[4];
        #pragma unroll
        for (int k = 0; k < 4; ++k) g4v[k] = contrib[k] + __shfl_xor_sync(FULL, contrib[k], 1);
        #pragma unroll
        for (int k = 0; k < 4; ++k) g4v[k] += __shfl_xor_sync(FULL, g4v[k], 2);
        #pragma unroll
        for (int k = 0; k < 4; ++k) g8v[k] = g4v[k] + __shfl_xor_sync(FULL, g4v[k], 4);
        if (pidx >= 0) {
            #pragma unroll
            for (int k = 0; k < 4; ++k) {
                const float f = (pidx == 0) ? g8v[k] : g4v[k];
                const float d = tr[k] - (f - mf) * rf;
                accC += d * d;
            }
        }
    };

    // pipelined main loop: loads of batch t+1 issue before shuffles of batch t
    loadB(sBeg, 0);
    #pragma unroll
    for (int t = 0; t < 4; ++t) {
        if (t >= nB) break;
        if (t + 1 < nB) loadB(sBeg + (t + 1) * 4, (t + 1) & 1);
        computeB(sBeg + t * 4, t & 1);
    }

    // ---- reductions ----
    #pragma unroll
    for (int off = 16; off; off >>= 1) {
        accA += __shfl_xor_sync(FULL, accA, off);
        accB += __shfl_xor_sync(FULL, accB, off);
        accC += __shfl_xor_sync(FULL, accC, off);
    }

    __shared__ double sA[WPB], sB[WPB], sC[WPB];
    if (lane == 0) {
        sA[warp] = (double)accA;
        sB[warp] = (double)accB;
        sC[warp] = (double)accC;
    }
    __syncthreads();

    if (warp == 0) {
        double a  = (lane < WPB) ? sA[lane] : 0.0;
        double bb = (lane < WPB) ? sB[lane] : 0.0;
        double c  = (lane < WPB) ? sC[lane] : 0.0;
        #pragma unroll
        for (int off = 4; off; off >>= 1) {
            a  += __shfl_xor_sync(FULL, a, off);
            bb += __shfl_xor_sync(FULL, bb, off);
            c  += __shfl_xor_sync(FULL, c, off);
        }
        if (lane == 0) {
            atomicAdd(&g_acc[0], a);
            atomicAdd(&g_acc[1], bb);
            atomicAdd(&g_acc[2], c);
            __threadfence();
            const unsigned t = atomicAdd(&g_ticket, 1u);
            if (t == (unsigned)(NBLK - 1)) {
                __threadfence();
                volatile double* ga = g_acc;
                const double A  = ga[0];
                const double B0 = ga[1];
                const double C  = ga[2];
                const double nA = (double)B_ * (double)(S_ - 1) * 72.0;
                const double nB2 = (double)B_ * 72.0;
                const double nC = (double)B_ * (double)(S_ - 1) * (double)VF_;
                const double loss1 = 10.0 * A / nA + 20.0 * B0 / nB2;
                const double loss2 = 10.0 * C / nC;
                out[0] = (float)(2.0 * loss1 + 1.5 * loss2);
                ga[0] = 0.0; ga[1] = 0.0; ga[2] = 0.0;
                g_ticket = 0;
            }
        }
    }
}

extern "C" void kernel_launch(void* const* d_in, const int* in_sizes, int n_in,
                              void* d_out, int out_size) {
    const float* pred = (const float*)d_in[0];   // predict_seq (B,S,F)
    // d_in[1] = _train_x1 (unused), d_in[2] = _train_x2 (unused)
    const float* tvft = (const float*)d_in[3];   // _true_vel_factor (B,S+1,VF)
    const float* mean = (const float*)d_in[4];   // _mean (F,)
    const float* stdv = (const float*)d_in[5];   // _std (F,)

    vel_loss_pipe<<<NBLK, 256>>>(pred, tvft, mean, stdv, (float*)d_out);
}

// round 8
// speedup vs baseline: 1.1170x; 1.1133x over previous
#include <cuda_runtime.h>

// VelocityLoss on GB300 — R4 dataflow (direct LDG, joint-per-lane, 4-row
// batches, simple loop) + occupancy fix: __launch_bounds__(256,4) caps regs
// at 64 -> 32 resident warps/SM (vs 24 at R4's 80 regs). Pointer-increment
// addressing trims integer register pressure to avoid spills at the cap.

namespace {
constexpr int B_  = 512;
constexpr int S_  = 480;
constexpr int F_  = 149;
constexpr int VF_ = 5;
constexpr int CH  = 16;                   // rows per warp chunk
constexpr int CPB = S_ / CH;              // 30
constexpr int WPB = 8;                    // 256 threads
constexpr int NBLK = B_ * CPB / WPB;      // 1920
}

__device__ double g_acc[3] = {0.0, 0.0, 0.0};
__device__ unsigned int g_ticket = 0;

// lane -> joint, part groups shuffle-aligned:
// lanes 0-7 part0, 8-11 part1, 12-15 part2, 16-19 part3, 20-23 part4
__constant__ int c_j[24] = {
    8, 9, 10, 11, 12, 21, 22, 23,
    0, 1, 2, 3,
    4, 5, 6, 7,
    13, 14, 15, 16,
    17, 18, 19, 20
};
__constant__ float c_wl[24] = {
    1.f/9, 1.f/9, 1.f/9, 1.f/9, 1.f/9, 1.f/9, 2.f/9, 1.f/9,
    0.1f, 0.2f, 0.3f, 0.4f,
    0.1f, 0.2f, 0.3f, 0.4f,
    0.1f, 0.2f, 0.3f, 0.4f,
    0.1f, 0.2f, 0.3f, 0.4f
};

__global__ void __launch_bounds__(256, 4) vel_loss_occ(
    const float* __restrict__ pred,   // (B, S, F)
    const float* __restrict__ tvft,   // (B, S+1, VF)
    const float* __restrict__ meanv,  // (F,)
    const float* __restrict__ stdv,   // (F,)
    float* __restrict__ out)
{
    const int tid  = threadIdx.x;
    const int lane = tid & 31;
    const int warp = tid >> 5;
    const int idx  = blockIdx.x * WPB + warp;
    const int b    = idx / CPB;
    const int s0   = (idx % CPB) * CH;
    const unsigned FULL = 0xffffffffu;

    // per-lane joint parameters
    int jj = 0; float w = 0.f;
    float sp0 = 0, sp1 = 0, sp2 = 0, mv0 = 0, mv1 = 0, mv2 = 0, rv0 = 0, rv1 = 0, rv2 = 0;
    const bool act = (lane < 24);
    if (act) {
        jj = c_j[lane] * 3;
        w  = c_wl[lane];
        sp0 = stdv[jj];       sp1 = stdv[jj + 1];       sp2 = stdv[jj + 2];
        mv0 = meanv[72 + jj]; mv1 = meanv[72 + jj + 1]; mv2 = meanv[72 + jj + 2];
        rv0 = 1.0f / stdv[72 + jj];
        rv1 = 1.0f / stdv[72 + jj + 1];
        rv2 = 1.0f / stdv[72 + jj + 2];
    }
    int pidx = -1;
    if      (lane == 0)  pidx = 0;
    else if (lane == 8)  pidx = 1;
    else if (lane == 12) pidx = 2;
    else if (lane == 16) pidx = 3;
    else if (lane == 20) pidx = 4;
    float mf = 0.f, rf = 0.f;
    if (pidx >= 0) { mf = meanv[144 + pidx]; rf = 1.0f / stdv[144 + pidx]; }

    float accA = 0.f, accB = 0.f, accC = 0.f;
    float p0 = 0.f, p1 = 0.f, p2 = 0.f;

    // running pointers (advanced, not recomputed)
    const float* r  = pred + ((size_t)(b * S_ + s0)) * F_;   // row s0
    const float* tr = tvft + ((size_t)(b * (S_ + 1) + s0)) * VF_ + (pidx >= 0 ? pidx : 0);

    int sBeg = s0;
    if (s0 == 0) {
        if (act) {
            p0 = r[jj]; p1 = r[jj + 1]; p2 = r[jj + 2];
            const float q0 = r[77 + jj], q1 = r[78 + jj], q2 = r[79 + jj];
            accB = q0 * q0 + q1 * q1 + q2 * q2;   // s==0 zero-target term
        }
        sBeg = 1;
        r  += F_;
        tr += VF_;
    } else if (act) {
        const float* rp = r - F_;
        p0 = rp[jj]; p1 = rp[jj + 1]; p2 = rp[jj + 2];
    }

    const int sEnd = s0 + CH;
    int s = sBeg;

    // main loop: 4-row batches
    for (; s + 4 <= sEnd; s += 4) {
        float c0[4], c1[4], c2[4], q0[4], q1[4], q2[4];
        {
            const float* rr = r;
            #pragma unroll
            for (int k = 0; k < 4; ++k, rr += F_) {
                if (act) {
                    c0[k] = rr[jj];      c1[k] = rr[jj + 1];  c2[k] = rr[jj + 2];
                    q0[k] = rr[77 + jj]; q1[k] = rr[78 + jj]; q2[k] = rr[79 + jj];
                }
            }
        }
        float trv[4] = {0.f, 0.f, 0.f, 0.f};
        if (pidx >= 0) {
            #pragma unroll
            for (int k = 0; k < 4; ++k) trv[k] = tr[k * VF_];
        }
        float contrib[4];
        #pragma unroll
        for (int k = 0; k < 4; ++k) {
            contrib[k] = 0.f;
            if (act) {
                const float v0 = (c0[k] - p0) * sp0;
                const float v1 = (c1[k] - p1) * sp1;
                const float v2 = (c2[k] - p2) * sp2;
                const float d0 = q0[k] - (v0 - mv0) * rv0;
                const float d1 = q1[k] - (v1 - mv1) * rv1;
                const float d2 = q2[k] - (v2 - mv2) * rv2;
                accA += d0 * d0 + d1 * d1 + d2 * d2;
                contrib[k] = sqrtf(v0 * v0 + v1 * v1 + v2 * v2) * w;
                p0 = c0[k]; p1 = c1[k]; p2 = c2[k];
            }
        }
        float g4v[4], g8v[4];
        #pragma unroll
        for (int k = 0; k < 4; ++k) g4v[k] = contrib[k] + __shfl_xor_sync(FULL, contrib[k], 1);
        #pragma unroll
        for (int k = 0; k < 4; ++k) g4v[k] += __shfl_xor_sync(FULL, g4v[k], 2);
        #pragma unroll
        for (int k = 0; k < 4; ++k) g8v[k] = g4v[k] + __shfl_xor_sync(FULL, g4v[k], 4);
        if (pidx >= 0) {
            #pragma unroll
            for (int k = 0; k < 4; ++k) {
                const float f = (pidx == 0) ? g8v[k] : g4v[k];
                const float d = trv[k] - (f - mf) * rf;
                accC += d * d;
            }
        }
        r  += 4 * F_;
        tr += 4 * VF_;
    }

    // tail (only the s0==0 chunk: 3 rows)
    for (; s < sEnd; ++s, r += F_, tr += VF_) {
        float contrib = 0.f;
        if (act) {
            const float cc0 = r[jj], cc1 = r[jj + 1], cc2 = r[jj + 2];
            const float qq0 = r[77 + jj], qq1 = r[78 + jj], qq2 = r[79 + jj];
            const float v0 = (cc0 - p0) * sp0;
            const float v1 = (cc1 - p1) * sp1;
            const float v2 = (cc2 - p2) * sp2;
            const float d0 = qq0 - (v0 - mv0) * rv0;
            const float d1 = qq1 - (v1 - mv1) * rv1;
            const float d2 = qq2 - (v2 - mv2) * rv2;
            accA += d0 * d0 + d1 * d1 + d2 * d2;
            contrib = sqrtf(v0 * v0 + v1 * v1 + v2 * v2) * w;
            p0 = cc0; p1 = cc1; p2 = cc2;
        }
        float g4v = contrib;
        g4v += __shfl_xor_sync(FULL, g4v, 1);
        g4v += __shfl_xor_sync(FULL, g4v, 2);
        const float g8v = g4v + __shfl_xor_sync(FULL, g4v, 4);
        if (pidx >= 0) {
            const float f = (pidx == 0) ? g8v : g4v;
            const float d = tr[0] - (f - mf) * rf;
            accC += d * d;
        }
    }

    // ---- reductions ----
    #pragma unroll
    for (int off = 16; off; off >>= 1) {
        accA += __shfl_xor_sync(FULL, accA, off);
        accB += __shfl_xor_sync(FULL, accB, off);
        accC += __shfl_xor_sync(FULL, accC, off);
    }

    __shared__ double sA[WPB], sB[WPB], sC[WPB];
    if (lane == 0) {
        sA[warp] = (double)accA;
        sB[warp] = (double)accB;
        sC[warp] = (double)accC;
    }
    __syncthreads();

    if (warp == 0) {
        double a  = (lane < WPB) ? sA[lane] : 0.0;
        double bb = (lane < WPB) ? sB[lane] : 0.0;
        double c  = (lane < WPB) ? sC[lane] : 0.0;
        #pragma unroll
        for (int off = 4; off; off >>= 1) {
            a  += __shfl_xor_sync(FULL, a, off);
            bb += __shfl_xor_sync(FULL, bb, off);
            c  += __shfl_xor_sync(FULL, c, off);
        }
        if (lane == 0) {
            atomicAdd(&g_acc[0], a);
            atomicAdd(&g_acc[1], bb);
            atomicAdd(&g_acc[2], c);
            __threadfence();
            const unsigned t = atomicAdd(&g_ticket, 1u);
            if (t == (unsigned)(NBLK - 1)) {
                __threadfence();
                volatile double* ga = g_acc;
                const double A  = ga[0];
                const double B0 = ga[1];
                const double C  = ga[2];
                const double nA  = (double)B_ * (double)(S_ - 1) * 72.0;
                const double nB2 = (double)B_ * 72.0;
                const double nC  = (double)B_ * (double)(S_ - 1) * (double)VF_;
                const double loss1 = 10.0 * A / nA + 20.0 * B0 / nB2;
                const double loss2 = 10.0 * C / nC;
                out[0] = (float)(2.0 * loss1 + 1.5 * loss2);
                ga[0] = 0.0; ga[1] = 0.0; ga[2] = 0.0;
                g_ticket = 0;
            }
        }
    }
}

extern "C" void kernel_launch(void* const* d_in, const int* in_sizes, int n_in,
                              void* d_out, int out_size) {
    const float* pred = (const float*)d_in[0];   // predict_seq (B,S,F)
    // d_in[1] = _train_x1 (unused), d_in[2] = _train_x2 (unused)
    const float* tvft = (const float*)d_in[3];   // _true_vel_factor (B,S+1,VF)
    const float* mean = (const float*)d_in[4];   // _mean (F,)
    const float* stdv = (const float*)d_in[5];   // _std (F,)

    vel_loss_occ<<<NBLK, 256>>>(pred, tvft, mean, stdv, (float*)d_out);
}